// round 1
// baseline (speedup 1.0000x reference)
#include <cuda_runtime.h>
#include <cuda_bf16.h>
#include <math.h>

// Problem constants (fixed shapes per reference): B=16, H=768, W=2048, N=32
#define HH 768
#define WW 2048
#define RPB 4          // rows per block (H % RPB == 0, and RPB divides within one image)
#define TPB 256        // threads per block
#define MAXN 64        // max boxes per image we support in shared

#define FG_W 13.0f

// Device-global scratch (no allocations allowed). Zero-initialized at module load;
// the finalizing block resets them so every graph replay sees clean state.
__device__ double       g_sum   = 0.0;
__device__ unsigned int g_count = 0u;

__global__ void __launch_bounds__(TPB)
balancer_kernel(const float* __restrict__ loss,
                const float* __restrict__ boxes,
                float* __restrict__ out,
                int N, double inv_num_pixels)
{
    __shared__ int   s_u1[RPB][MAXN];
    __shared__ int   s_u2[RPB][MAXN];
    __shared__ int   s_cnt[RPB];
    __shared__ float s_warp[TPB / 32];

    const int tid  = threadIdx.x;
    const int row0 = blockIdx.x * RPB;          // global row index (b*H + h)
    const int b    = row0 / HH;
    const int h0   = row0 - b * HH;             // image-local first row

    if (tid < RPB) s_cnt[tid] = 0;
    __syncthreads();

    // Build per-row active column-interval lists (boxes whose [floor(y1), ceil(y2)) covers the row)
    for (int t = tid; t < RPB * N; t += TPB) {
        const int r = t / N;
        const int j = t - r * N;
        const float* bx = boxes + ((size_t)b * N + j) * 4;
        const float x1 = bx[0], y1 = bx[1], x2 = bx[2], y2 = bx[3];
        const int v1 = (int)floorf(y1);
        const int v2 = (int)ceilf(y2);
        const int h  = h0 + r;
        if (h >= v1 && h < v2) {
            const int pos = atomicAdd(&s_cnt[r], 1);
            s_u1[r][pos] = (int)floorf(x1);
            s_u2[r][pos] = (int)ceilf(x2);
        }
    }
    __syncthreads();

    // Stream RPB*WW pixels with coalesced float4 loads.
    const float4* __restrict__ base = (const float4*)(loss + (size_t)row0 * WW);
    float acc = 0.0f;

    constexpr int VECS_TOTAL = (RPB * WW) / 4;      // 2048 float4s
    constexpr int ITERS      = VECS_TOTAL / TPB;    // 8 iterations

    #pragma unroll
    for (int i = 0; i < ITERS; i++) {
        const int q   = i * TPB + tid;
        const float4 v = base[q];
        const int idx = q * 4;
        const int r   = idx / WW;
        const int c0  = idx & (WW - 1);
        const int cnt = s_cnt[r];
        const int* __restrict__ u1 = s_u1[r];
        const int* __restrict__ u2 = s_u2[r];

        const float vals[4] = {v.x, v.y, v.z, v.w};
        #pragma unroll
        for (int j = 0; j < 4; j++) {
            const int c = c0 + j;
            bool fg = false;
            for (int k = 0; k < cnt; k++) {
                if (c >= u1[k] && c < u2[k]) { fg = true; break; }
            }
            acc += fg ? vals[j] * FG_W : vals[j];
        }
    }

    // Block reduction: warp shuffles, then cross-warp via shared.
    #pragma unroll
    for (int o = 16; o; o >>= 1) acc += __shfl_xor_sync(0xffffffffu, acc, o);
    const int warp = tid >> 5, lane = tid & 31;
    if (lane == 0) s_warp[warp] = acc;
    __syncthreads();
    if (warp == 0) {
        float wsum = (lane < TPB / 32) ? s_warp[lane] : 0.0f;
        #pragma unroll
        for (int o = 4; o; o >>= 1) wsum += __shfl_xor_sync(0xffffffffu, wsum, o);
        if (lane == 0) {
            atomicAdd(&g_sum, (double)wsum);
            __threadfence();
            const unsigned int ticket = atomicAdd(&g_count, 1u);
            if (ticket == gridDim.x - 1) {
                // All partial sums are visible (their atomics + fences happened-before
                // the last ticket increment we just observed).
                const double s = atomicAdd(&g_sum, 0.0);   // coherent L2 read
                out[0] = (float)(s * inv_num_pixels);
                // Reset for the next (graph-replayed) invocation.
                atomicExch((unsigned long long*)&g_sum, 0ull);
                atomicExch(&g_count, 0u);
                __threadfence();
            }
        }
    }
}

extern "C" void kernel_launch(void* const* d_in, const int* in_sizes, int n_in,
                              void* d_out, int out_size)
{
    const float* loss  = (const float*)d_in[0];
    const float* boxes = (const float*)d_in[1];
    // d_in[2] = num_gt_per_img (device int) — N derived from host-visible sizes instead.

    const int total_px = in_sizes[0];              // B*H*W
    const int B        = total_px / (HH * WW);     // 16
    const int n_total  = in_sizes[1] / 4;          // B*N
    const int N        = n_total / B;              // 32

    const double inv_num_pixels = 1.0 / (double)total_px;

    const int nblocks = (B * HH) / RPB;            // 3072
    balancer_kernel<<<nblocks, TPB>>>(loss, boxes, (float*)d_out, N, inv_num_pixels);
}

// round 2
// speedup vs baseline: 4.3068x; 4.3068x over previous
#include <cuda_runtime.h>
#include <cuda_bf16.h>
#include <math.h>

// Fixed shapes per reference: B=16, H=768, W=2048, N=32
#define HH 768
#define WW 2048
#define RPB 4          // rows per block
#define TPB 256        // threads per block
#define MAXN 64        // max boxes per image supported
#define WPR (WW / 32)  // 64 mask words per row

#define FG_W 13.0f

// Device-global scratch (no allocs allowed). Reset by the finalizing block so
// every graph replay sees clean state.
__device__ double       g_sum   = 0.0;
__device__ unsigned int g_count = 0u;

__global__ void __launch_bounds__(TPB)
balancer_kernel(const float* __restrict__ loss,
                const float* __restrict__ boxes,
                float* __restrict__ out,
                int N, double inv_num_pixels)
{
    __shared__ int      s_u1[RPB][MAXN];
    __shared__ int      s_u2[RPB][MAXN];
    __shared__ int      s_cnt[RPB];
    __shared__ unsigned s_mask[RPB][WPR];     // per-row fg column bitmask
    __shared__ float    s_warp[TPB / 32];

    const int tid  = threadIdx.x;
    const int row0 = blockIdx.x * RPB;        // global row (b*H + h)
    const int b    = row0 / HH;
    const int h0   = row0 - b * HH;

    if (tid < RPB) s_cnt[tid] = 0;
    __syncthreads();

    // Phase 1a: per-row active interval lists (boxes covering each row).
    for (int t = tid; t < RPB * N; t += TPB) {
        const int r = t / N;
        const int j = t - r * N;
        const float* bx = boxes + ((size_t)b * N + j) * 4;
        const float x1 = bx[0], y1 = bx[1], x2 = bx[2], y2 = bx[3];
        const int v1 = (int)floorf(y1);
        const int v2 = (int)ceilf(y2);
        const int h  = h0 + r;
        if (h >= v1 && h < v2) {
            const int pos = atomicAdd(&s_cnt[r], 1);
            s_u1[r][pos] = (int)floorf(x1);
            s_u2[r][pos] = (int)ceilf(x2);
        }
    }
    __syncthreads();

    // Phase 1b: rasterize intervals into 32-column bitmask words.
    // TPB == RPB * WPR == 256, one word per thread.
    {
        const int r     = tid >> 6;           // tid / WPR
        const int wi    = tid & (WPR - 1);
        const int wbase = wi << 5;
        const int cnt   = s_cnt[r];
        unsigned m = 0u;
        for (int k = 0; k < cnt; k++) {
            int lo = s_u1[r][k] - wbase;
            int hi = s_u2[r][k] - wbase;
            lo = lo < 0 ? 0 : lo;
            hi = hi > 32 ? 32 : hi;
            if (hi > lo) {
                const int len = hi - lo;
                const unsigned span = (len >= 32) ? 0xffffffffu : ((1u << len) - 1u);
                m |= span << lo;
            }
        }
        s_mask[r][wi] = m;
    }
    __syncthreads();

    // Phase 2: stream RPB*WW pixels, branchless bit-test weighting.
    const float4* __restrict__ base = (const float4*)(loss + (size_t)row0 * WW);
    float acc = 0.0f;

    constexpr int VECS_TOTAL = (RPB * WW) / 4;    // 2048 float4s
    constexpr int ITERS      = VECS_TOTAL / TPB;  // 8

    #pragma unroll
    for (int i = 0; i < ITERS; i++) {
        const int    q    = i * TPB + tid;
        const float4 v    = base[q];
        const int    idx  = q * 4;
        const int    r    = idx / WW;             // constant-folded shifts
        const int    c0   = idx & (WW - 1);
        const unsigned word = s_mask[r][c0 >> 5];
        const unsigned nib  = word >> (c0 & 31);  // bits 0..3 = our 4 columns

        acc = fmaf(v.x, (nib & 1u) ? FG_W : 1.0f, acc);
        acc = fmaf(v.y, (nib & 2u) ? FG_W : 1.0f, acc);
        acc = fmaf(v.z, (nib & 4u) ? FG_W : 1.0f, acc);
        acc = fmaf(v.w, (nib & 8u) ? FG_W : 1.0f, acc);
    }

    // Block reduction.
    #pragma unroll
    for (int o = 16; o; o >>= 1) acc += __shfl_xor_sync(0xffffffffu, acc, o);
    const int warp = tid >> 5, lane = tid & 31;
    if (lane == 0) s_warp[warp] = acc;
    __syncthreads();
    if (warp == 0) {
        float wsum = (lane < TPB / 32) ? s_warp[lane] : 0.0f;
        #pragma unroll
        for (int o = 4; o; o >>= 1) wsum += __shfl_xor_sync(0xffffffffu, wsum, o);
        if (lane == 0) {
            atomicAdd(&g_sum, (double)wsum);
            __threadfence();
            const unsigned ticket = atomicAdd(&g_count, 1u);
            if (ticket == gridDim.x - 1) {
                const double s = atomicAdd(&g_sum, 0.0);   // coherent read
                out[0] = (float)(s * inv_num_pixels);
                atomicExch((unsigned long long*)&g_sum, 0ull);
                atomicExch(&g_count, 0u);
                __threadfence();
            }
        }
    }
}

extern "C" void kernel_launch(void* const* d_in, const int* in_sizes, int n_in,
                              void* d_out, int out_size)
{
    const float* loss  = (const float*)d_in[0];
    const float* boxes = (const float*)d_in[1];

    const int total_px = in_sizes[0];             // B*H*W
    const int B        = total_px / (HH * WW);    // 16
    const int n_total  = in_sizes[1] / 4;         // B*N
    const int N        = n_total / B;             // 32

    const double inv_num_pixels = 1.0 / (double)total_px;

    const int nblocks = (B * HH) / RPB;           // 3072
    balancer_kernel<<<nblocks, TPB>>>(loss, boxes, (float*)d_out, N, inv_num_pixels);
}